// round 8
// baseline (speedup 1.0000x reference)
#include <cuda_runtime.h>

// XY model log-density: out[s] = sum_i cos(x[up(i)] - x[i]) + cos(x[right(i)] - x[i])
// 64x64 lattice (4096 sites), 16384 samples, BETA = 1.
//
// R8: R7 + pipe balancing. 1 of 8 bonds per iteration is computed with an
// FMA-pipe polynomial (half-angle + even Taylor deg-14, err <= 4e-6) instead
// of MUFU.COS. MUFU (est. ~73% busy, not shown by ncu summary) and DRAM (81%)
// are co-binding; fma pipe sits at 27% -> shift work onto it.

#define LATTICE 4096
#define THREADS 256

// cos(d) for d in (-2pi, 2pi): y=d/2 in (-pi,pi), even Taylor through u^7,
// then double: cos(d) = 2*cos^2(y) - 1. Pure FMA-pipe.
__device__ __forceinline__ float cos_poly(float d)
{
    const float y = 0.5f * d;
    const float u = y * y;
    float p = -1.1470746e-11f;
    p = fmaf(p, u,  2.0876757e-9f);
    p = fmaf(p, u, -2.7557319e-7f);
    p = fmaf(p, u,  2.4801587e-5f);
    p = fmaf(p, u, -1.3888889e-3f);
    p = fmaf(p, u,  4.1666668e-2f);
    p = fmaf(p, u, -0.5f);
    p = fmaf(p, u,  1.0f);              // p = cos(y)
    return fmaf(p + p, p, -1.0f);       // 2p^2 - 1
}

__global__ __launch_bounds__(THREADS) void xy_hamiltonian_kernel(
    const float* __restrict__ state,
    float* __restrict__ out)
{
    __shared__ float warp_sums[THREADS / 32];

    const int tid  = threadIdx.x;
    const int lane = tid & 31;
    const float4* __restrict__ rp4 =
        reinterpret_cast<const float4*>(state + (size_t)blockIdx.x * LATTICE);

    // Right-neighbor source lane: within each 16-lane group (one 64-site
    // lattice row = 16 float4), lane L's boundary right-neighbor is lane
    // L+1's a.x, wrapping to the group's first lane at col 63.
    const int src_lane = (lane & ~15) | ((lane + 1) & 15);

    float acc  = 0.0f;   // MUFU-side accumulator
    float accp = 0.0f;   // poly-side accumulator (independent chain)
    #pragma unroll
    for (int k = 0; k < 4; k++) {
        const int m = tid + k * THREADS;                           // float4 idx 0..1023
        const float4 a = __ldcs(&rp4[m]);                          // own sites
        const float4 b = __ldcs(&rp4[(m + 16) & (LATTICE/4 - 1)]); // up neighbors (+64, periodic)
        const float xr3 = __shfl_sync(0xffffffffu, a.x, src_lane);

        acc += __cosf(b.x - a.x);   // up bonds (MUFU)
        acc += __cosf(b.y - a.y);
        acc += __cosf(b.z - a.z);
        acc += __cosf(b.w - a.w);
        acc += __cosf(a.y - a.x);   // right bonds
        accp += cos_poly(a.z - a.y);   // <- offloaded to FMA pipe
        acc += __cosf(a.w - a.z);
        acc += __cosf(xr3 - a.w);
    }
    acc += accp;

    // Warp reduce
    #pragma unroll
    for (int o = 16; o > 0; o >>= 1)
        acc += __shfl_down_sync(0xffffffffu, acc, o);
    if (lane == 0)
        warp_sums[tid >> 5] = acc;
    __syncthreads();

    if (tid < 8) {
        float v = warp_sums[tid];
        #pragma unroll
        for (int o = 4; o > 0; o >>= 1)
            v += __shfl_down_sync(0x000000ffu, v, o);
        if (tid == 0)
            out[blockIdx.x] = v;
    }
}

extern "C" void kernel_launch(void* const* d_in, const int* in_sizes, int n_in,
                              void* d_out, int out_size)
{
    const float* state = (const float*)d_in[0];
    // d_in[1] (shift table, int64) is reproduced arithmetically in-kernel.
    float* out = (float*)d_out;

    const int n_samples = in_sizes[0] / LATTICE;  // 16384
    xy_hamiltonian_kernel<<<n_samples, THREADS>>>(state, out);
}